// round 2
// baseline (speedup 1.0000x reference)
#include <cuda_runtime.h>
#include <math.h>

// Problem constants (fixed by the dataset)
#define N_PTS 16384
#define HDIM  256
#define KSEL  7
#define NCHUNK 8
#define CHUNK (N_PTS / NCHUNK)      // 2048
#define ROWS_PER_BLK 256
#define MT 16                       // rows per block in the MLP kernel
#define HTOT 384                    // concat hidden: 256 (coord) + 128 (dist)
#define GBIN 64                     // 64x64 Morton bins
#define NBIN (GBIN * GBIN)

// Scratch (__device__ globals; no allocation allowed)
__device__ float  g_part[N_PTS * NCHUNK * KSEL];
__device__ float  g_mean[N_PTS];
__device__ float4 g_p4[N_PTS];          // sorted {x, y, x^2+y^2, orig_idx_bits}
__device__ int    g_binCnt[NBIN];
__device__ int    g_binCursor[NBIN];

// ---------------------------------------------------------------------------
// Morton binning helpers (bbox hardcoded [-60,60]; clamping only affects
// sort order, never correctness -- kNN below is still exact brute force).
// ---------------------------------------------------------------------------
__device__ __forceinline__ unsigned spread8(unsigned v) {
    v &= 0xFFu;
    v = (v | (v << 4)) & 0x0F0Fu;
    v = (v | (v << 2)) & 0x3333u;
    v = (v | (v << 1)) & 0x5555u;
    return v;
}
__device__ __forceinline__ int bin_of(float x, float y) {
    float fx = (x + 60.0f) * (GBIN / 120.0f);
    float fy = (y + 60.0f) * (GBIN / 120.0f);
    int bx = min(max(__float2int_rd(fx), 0), GBIN - 1);
    int by = min(max(__float2int_rd(fy), 0), GBIN - 1);
    return (int)(spread8((unsigned)bx) | (spread8((unsigned)by) << 1));
}

// ---------------------------------------------------------------------------
// Sort pipeline: zero counts -> histogram -> scan -> scatter
// ---------------------------------------------------------------------------
__global__ void kinit() {
    int i = blockIdx.x * blockDim.x + threadIdx.x;
    if (i < NBIN) g_binCnt[i] = 0;
}

__global__ void khist(const float2* __restrict__ pts) {
    int i = blockIdx.x * blockDim.x + threadIdx.x;
    float2 p = pts[i];
    atomicAdd(&g_binCnt[bin_of(p.x, p.y)], 1);
}

__global__ void __launch_bounds__(1024) kscan() {
    __shared__ int warpsum[32];
    const int t    = threadIdx.x;
    const int lane = t & 31;
    const int wid  = t >> 5;
    const int b0   = t * 4;

    int c0 = g_binCnt[b0 + 0];
    int c1 = g_binCnt[b0 + 1];
    int c2 = g_binCnt[b0 + 2];
    int c3 = g_binCnt[b0 + 3];
    int tot = c0 + c1 + c2 + c3;

    int v = tot;
    #pragma unroll
    for (int off = 1; off < 32; off <<= 1) {
        int n = __shfl_up_sync(0xFFFFFFFFu, v, off);
        if (lane >= off) v += n;
    }
    if (lane == 31) warpsum[wid] = v;
    __syncthreads();
    if (wid == 0) {
        int w = warpsum[lane];
        #pragma unroll
        for (int off = 1; off < 32; off <<= 1) {
            int n = __shfl_up_sync(0xFFFFFFFFu, w, off);
            if (lane >= off) w += n;
        }
        warpsum[lane] = w;
    }
    __syncthreads();

    int base = v - tot + (wid ? warpsum[wid - 1] : 0);  // exclusive prefix
    g_binCursor[b0 + 0] = base;
    g_binCursor[b0 + 1] = base + c0;
    g_binCursor[b0 + 2] = base + c0 + c1;
    g_binCursor[b0 + 3] = base + c0 + c1 + c2;
}

__global__ void kscatter(const float2* __restrict__ pts) {
    int i = blockIdx.x * blockDim.x + threadIdx.x;
    float2 p = pts[i];
    int b = bin_of(p.x, p.y);
    int pos = atomicAdd(&g_binCursor[b], 1);
    float s = fmaf(p.x, p.x, p.y * p.y);
    g_p4[pos] = make_float4(p.x, p.y, s, __int_as_float(i));
}

// ---------------------------------------------------------------------------
// Kernel: partial top-7 of shifted squared distances per (sorted row, chunk).
// d2eff_j = s_j - 2*(x_j*xi + y_j*yi); true d2 = d2eff + s_i (added in merge).
// Shift is row-constant -> ranking preserved exactly. Insert chain is a
// REAL branch (rare + warp-coherent thanks to the spatial sort).
// ---------------------------------------------------------------------------
#define INS7(d) do {                                                 \
    if ((d) < t6) {                                                  \
        t6 = (d); float tt;                                          \
        if (t6 < t5) { tt = t5; t5 = t6; t6 = tt; }                  \
        if (t5 < t4) { tt = t4; t4 = t5; t5 = tt; }                  \
        if (t4 < t3) { tt = t3; t3 = t4; t4 = tt; }                  \
        if (t3 < t2) { tt = t2; t2 = t3; t3 = tt; }                  \
        if (t2 < t1) { tt = t1; t1 = t2; t2 = tt; }                  \
        if (t1 < t0) { tt = t0; t0 = t1; t1 = tt; }                  \
    }                                                                \
} while (0)

__global__ void __launch_bounds__(ROWS_PER_BLK)
knn_partial() {
    __shared__ __align__(16) float4 tile[CHUNK];   // 32 KB

    const int i     = blockIdx.x * ROWS_PER_BLK + threadIdx.x;  // sorted row
    const int cbase = blockIdx.y * CHUNK;

    for (int t = threadIdx.x; t < CHUNK; t += ROWS_PER_BLK)
        tile[t] = g_p4[cbase + t];
    __syncthreads();

    const float4 me = g_p4[i];
    const float c1 = -2.0f * me.x;
    const float c2 = -2.0f * me.y;

    float t0 = 1e30f, t1 = 1e30f, t2 = 1e30f, t3 = 1e30f,
          t4 = 1e30f, t5 = 1e30f, t6 = 1e30f;

    #pragma unroll 4
    for (int j = 0; j < CHUNK; j += 2) {
        const float4 p = tile[j];
        const float4 q = tile[j + 1];
        const float da = fmaf(p.y, c2, fmaf(p.x, c1, p.z));
        const float db = fmaf(q.y, c2, fmaf(q.x, c1, q.z));
        if (__builtin_expect(fminf(da, db) < t6, 0)) {
            asm volatile("" ::: "memory");   // defeat if-conversion
            INS7(da);
            INS7(db);
        }
    }

    float* out = g_part + (size_t)(i * NCHUNK + blockIdx.y) * KSEL;
    out[0] = t0; out[1] = t1; out[2] = t2; out[3] = t3;
    out[4] = t4; out[5] = t5; out[6] = t6;
}

// ---------------------------------------------------------------------------
// Merge 8 partial lists -> global top-7 -> add back s_i, drop self (t0),
// mean of 6 NN distances, written at the ORIGINAL row index.
// ---------------------------------------------------------------------------
__global__ void __launch_bounds__(256)
knn_merge() {
    const int i = blockIdx.x * 256 + threadIdx.x;   // sorted row
    const float* p = g_part + (size_t)i * NCHUNK * KSEL;

    float t0 = 1e30f, t1 = 1e30f, t2 = 1e30f, t3 = 1e30f,
          t4 = 1e30f, t5 = 1e30f, t6 = 1e30f;
    #pragma unroll
    for (int s = 0; s < NCHUNK * KSEL; ++s) {
        const float d = p[s];
        INS7(d);
    }

    const float4 me = g_p4[i];
    const float si  = me.z;
    const int orig  = __float_as_int(me.w);

    const float s1 = sqrtf(fmaxf(t1 + si, 1e-12f));
    const float s2 = sqrtf(fmaxf(t2 + si, 1e-12f));
    const float s3 = sqrtf(fmaxf(t3 + si, 1e-12f));
    const float s4 = sqrtf(fmaxf(t4 + si, 1e-12f));
    const float s5 = sqrtf(fmaxf(t5 + si, 1e-12f));
    const float s6 = sqrtf(fmaxf(t6 + si, 1e-12f));
    g_mean[orig] = (s1 + s2 + s3 + s4 + s5 + s6) * (1.0f / 6.0f);
}

// ---------------------------------------------------------------------------
// Fused MLPs with packed fma.rn.f32x2 (2 FMAs per instruction).
// Hidden tile stored transposed: hs[k*MT + m] so row-pairs are contiguous.
// Each thread owns one output column c; acc[a] packs rows {2a, 2a+1}.
// ---------------------------------------------------------------------------
#define FMA2(acc, a, b) \
    asm("fma.rn.f32x2 %0, %1, %2, %0;" : "+l"(acc) : "l"(a), "l"(b))

__global__ void __launch_bounds__(256)
fused_mlp(const float2* __restrict__ coords,
          const float*  __restrict__ W1,  const float* __restrict__ b1,
          const float*  __restrict__ W2,  const float* __restrict__ b2,
          const float*  __restrict__ Wd1, const float* __restrict__ bd1,
          const float*  __restrict__ Wd2, const float* __restrict__ bd2,
          float* __restrict__ out) {
    __shared__ __align__(16) float hs[HTOT * MT];   // 24 KB, [k][m]

    const int r0 = blockIdx.x * MT;

    // Phase A: layer-1 + SiLU for MT rows x 384 concat features
    for (int e = threadIdx.x; e < HTOT * MT; e += 256) {
        const int m  = e & (MT - 1);
        const int kk = e / MT;
        const int r  = r0 + m;
        float v;
        if (kk < HDIM) {
            const float2 c = coords[r];
            v = fmaf(c.x, W1[kk], fmaf(c.y, W1[HDIM + kk], b1[kk]));
        } else {
            const int q = kk - HDIM;
            v = fmaf(g_mean[r], Wd1[q], bd1[q]);
        }
        hs[e] = v / (1.0f + __expf(-v));
    }
    __syncthreads();

    // Phase B: packed dual-row accumulation
    const int c = threadIdx.x;
    unsigned long long acc[MT / 2];
    {
        const float binit = b2[c] + bd2[c];
        unsigned long long b2p;
        asm("mov.b64 %0, {%1, %1};" : "=l"(b2p) : "f"(binit));
        #pragma unroll
        for (int a = 0; a < MT / 2; ++a) acc[a] = b2p;
    }

    #pragma unroll 2
    for (int k = 0; k < HDIM; ++k) {
        const float w = W2[k * HDIM + c];
        unsigned long long w2;
        asm("mov.b64 %0, {%1, %1};" : "=l"(w2) : "f"(w));
        const ulonglong2* hp = reinterpret_cast<const ulonglong2*>(hs + k * MT);
        #pragma unroll
        for (int p = 0; p < MT / 4; ++p) {
            const ulonglong2 h = hp[p];
            FMA2(acc[2 * p],     h.x, w2);
            FMA2(acc[2 * p + 1], h.y, w2);
        }
    }
    #pragma unroll 2
    for (int k = 0; k < HTOT - HDIM; ++k) {
        const float w = Wd2[k * HDIM + c];
        unsigned long long w2;
        asm("mov.b64 %0, {%1, %1};" : "=l"(w2) : "f"(w));
        const ulonglong2* hp =
            reinterpret_cast<const ulonglong2*>(hs + (HDIM + k) * MT);
        #pragma unroll
        for (int p = 0; p < MT / 4; ++p) {
            const ulonglong2 h = hp[p];
            FMA2(acc[2 * p],     h.x, w2);
            FMA2(acc[2 * p + 1], h.y, w2);
        }
    }

    #pragma unroll
    for (int a = 0; a < MT / 2; ++a) {
        float lo, hi;
        asm("mov.b64 {%0, %1}, %2;" : "=f"(lo), "=f"(hi) : "l"(acc[a]));
        out[(size_t)(r0 + 2 * a)     * HDIM + c] = lo;
        out[(size_t)(r0 + 2 * a + 1) * HDIM + c] = hi;
    }
}

// ---------------------------------------------------------------------------
// Launch. Inputs: 0 coords | 1 W1 | 2 b1 | 3 W2 | 4 b2 | 5 Wd1 | 6 bd1
//                 7 Wd2 | 8 bd2 | 9 k (fixed = 6)
// ---------------------------------------------------------------------------
extern "C" void kernel_launch(void* const* d_in, const int* in_sizes, int n_in,
                              void* d_out, int out_size) {
    const float2* coords = (const float2*)d_in[0];
    const float*  W1     = (const float*)d_in[1];
    const float*  b1     = (const float*)d_in[2];
    const float*  W2     = (const float*)d_in[3];
    const float*  b2     = (const float*)d_in[4];
    const float*  Wd1    = (const float*)d_in[5];
    const float*  bd1    = (const float*)d_in[6];
    const float*  Wd2    = (const float*)d_in[7];
    const float*  bd2    = (const float*)d_in[8];
    float* out = (float*)d_out;

    kinit<<<NBIN / 256, 256>>>();
    khist<<<N_PTS / 256, 256>>>(coords);
    kscan<<<1, 1024>>>();
    kscatter<<<N_PTS / 256, 256>>>(coords);

    dim3 g1(N_PTS / ROWS_PER_BLK, NCHUNK);
    knn_partial<<<g1, ROWS_PER_BLK>>>();
    knn_merge<<<N_PTS / 256, 256>>>();
    fused_mlp<<<N_PTS / MT, 256>>>(coords, W1, b1, W2, b2,
                                   Wd1, bd1, Wd2, bd2, out);
}